// round 10
// baseline (speedup 1.0000x reference)
#include <cuda_runtime.h>
#include <cuda_bf16.h>
#include <cstdint>

#define T_LEN 4000
#define HALF  2000
#define BLOCK 128
#define SEG   16
#define NSEG  125
#define P16(i) ((i) + (((i) >> 5) << 2))
#define BUFSZ 2248   // P16(1999)+1 -> 8992 bytes (output staging only)

#define S_C    (512.0f / 1323.0f)
#define OMS_C  (1.0f - 512.0f / 1323.0f)
#define LAMBDA 3.98320e-4f      // OMS_C^16

__device__ __forceinline__ float fast_exp2(float x) {
    float y; asm("ex2.approx.ftz.f32 %0, %1;" : "=f"(y) : "f"(x)); return y;
}
__device__ __forceinline__ float fast_log2(float x) {
    float y; asm("lg2.approx.ftz.f32 %0, %1;" : "=f"(y) : "f"(x)); return y;
}
__device__ __forceinline__ float fast_sqrt(float x) {
    float y; asm("sqrt.approx.ftz.f32 %0, %1;" : "=f"(y) : "f"(x)); return y;
}

struct Params { float delta, r, dr, nalpha; bool rhalf; };

__device__ __forceinline__ float pcen_elem(float xv, float M, const Params& p) {
    float L    = fast_log2(1e-6f + M);
    float sinv = fast_exp2(p.nalpha * L);
    float bse  = fmaf(xv, sinv, p.delta);            // > 0
    return (p.rhalf ? fast_sqrt(bse)
                    : fast_exp2(p.r * fast_log2(bse))) - p.dr;
}

__device__ __forceinline__ float horner4(float M, float4 v) {
    M = OMS_C * M + S_C * v.x;
    M = OMS_C * M + S_C * v.y;
    M = OMS_C * M + S_C * v.z;
    M = OMS_C * M + S_C * v.w;
    return M;
}

__global__ __launch_bounds__(BLOCK) void pcen_kernel(
    const float* __restrict__ x,
    const float* __restrict__ alpha_p,
    const float* __restrict__ delta_p,
    const float* __restrict__ r_p,
    float* __restrict__ out)
{
    __shared__ __align__(16) float buf[BUFSZ];   // output staging
    __shared__ float As[BLOCK];                  // As[t+2] = A_t; As[0..1] halo/x0

    const int u    = blockIdx.x;        // unit = 2*row + half
    const int tid  = threadIdx.x;
    const int row  = u >> 1;
    const int half = u & 1;

    const float* __restrict__ xh = x + (size_t)row * T_LEN + half * HALF;

    // scalar params (L1-broadcast)
    Params p;
    {
        float alpha = fminf(fmaxf(alpha_p[0], 0.01f), 0.99f);
        p.delta  = fabsf(delta_p[0]) + 1e-6f;
        p.r      = fminf(fmaxf(r_p[0], 0.01f), 1.0f);
        p.rhalf  = (p.r == 0.5f);
        p.dr     = p.rhalf ? fast_sqrt(p.delta)
                           : fast_exp2(p.r * fast_log2(p.delta));
        p.nalpha = -alpha;
    }

    const bool act = tid < NSEG;
    const int  s0  = SEG * tid;         // segment start within half

    // ---- A pass: zero-seeded Horner over own 16 values (LDG -> DRAM read) ----
    if (act) {
        float A = 0.0f;
        #pragma unroll
        for (int q = 0; q < 4; q++) {
            float4 v = *(const float4*)(xh + s0 + 4 * q);
            A = horner4(A, v);
        }
        As[tid + 2] = A;
        if (half == 0 && tid == 0)
            As[1] = *(xh);              // publish x[0] for tid1's exact boundary
    } else if (half && tid < NSEG + 2) {
        // threads 125,126: halo segment A's (x[1968..1983], x[1984..1999])
        const float* hsrc = x + (size_t)row * T_LEN + (HALF - 32) + (tid - NSEG) * SEG;
        float A = 0.0f;
        #pragma unroll
        for (int q = 0; q < 4; q++) {
            float4 v = *(const float4*)(hsrc + 4 * q);
            A = horner4(A, v);
        }
        As[tid - NSEG] = A;             // As[0], As[1]
    }
    __syncthreads();                    // BAR1: As visible

    // ---- window combine + compute (input re-read: L1 hits) ----
    if (act) {
        float M;
        if (half || tid >= 2) {
            M = fmaf(LAMBDA, As[tid], As[tid + 1]);      // A_{t-1} + lam*A_{t-2}
        } else if (tid == 0) {
            M = *(xh);                   // seed: first step yields M[0]=x[0]
        } else {                         // tid==1: exact M[15] = A_0 + lam*x0
            M = fmaf(LAMBDA, As[1], As[2]);
        }
        #pragma unroll
        for (int q = 0; q < 4; q++) {
            float4 v = *(const float4*)(xh + s0 + 4 * q);
            float4 o;
            M = OMS_C * M + S_C * v.x;  o.x = pcen_elem(v.x, M, p);
            M = OMS_C * M + S_C * v.y;  o.y = pcen_elem(v.y, M, p);
            M = OMS_C * M + S_C * v.z;  o.z = pcen_elem(v.z, M, p);
            M = OMS_C * M + S_C * v.w;  o.w = pcen_elem(v.w, M, p);
            *(float4*)&buf[P16(s0 + 4 * q)] = o;
        }
    }
    __syncthreads();                    // BAR2: results staged

    // ---- coalesced writeback ----
    {
        float* __restrict__ outr = out + (size_t)row * T_LEN + half * HALF;
        #pragma unroll
        for (int i = tid; i < 500; i += BLOCK) {
            float4 v = *(const float4*)&buf[P16(4 * i)];
            *(float4*)(outr + 4 * i) = v;
        }
    }
}

extern "C" void kernel_launch(void* const* d_in, const int* in_sizes, int n_in,
                              void* d_out, int out_size) {
    const float* mel   = (const float*)d_in[0];
    const float* alpha = (const float*)d_in[1];
    const float* delta = (const float*)d_in[2];
    const float* r     = (const float*)d_in[3];
    float* out = (float*)d_out;

    int rows = out_size / T_LEN;       // 16384
    pcen_kernel<<<2 * rows, BLOCK>>>(mel, alpha, delta, r, out);
}

// round 11
// speedup vs baseline: 1.2082x; 1.2082x over previous
#include <cuda_runtime.h>
#include <cuda_bf16.h>
#include <cstdint>

#define T_LEN  4000
#define QTR    1000
#define BLOCK  128
#define SEG    8
#define NSEG   125
#define HALO   24
#define P16(i) ((i) + (((i) >> 5) << 2))
#define BUFSZ  1148   // P16(HALO + QTR - 1) + 1 -> 4592 bytes

#define S_C    (512.0f / 1323.0f)
#define OMS_C  (1.0f - 512.0f / 1323.0f)
#define LAM8   1.9938299e-2f    // OMS_C^8

__device__ __forceinline__ float fast_exp2(float x) {
    float y; asm("ex2.approx.ftz.f32 %0, %1;" : "=f"(y) : "f"(x)); return y;
}
__device__ __forceinline__ float fast_log2(float x) {
    float y; asm("lg2.approx.ftz.f32 %0, %1;" : "=f"(y) : "f"(x)); return y;
}
__device__ __forceinline__ float fast_sqrt(float x) {
    float y; asm("sqrt.approx.ftz.f32 %0, %1;" : "=f"(y) : "f"(x)); return y;
}
__device__ __forceinline__ void cp_async16(uint32_t dst, const float* src) {
    asm volatile("cp.async.cg.shared.global [%0], [%1], 16;\n" :: "r"(dst), "l"(src));
}

struct Params { float delta, r, dr, nalpha; bool rhalf; };

__device__ __forceinline__ float pcen_elem(float xv, float M, const Params& p) {
    float L    = fast_log2(1e-6f + M);
    float sinv = fast_exp2(p.nalpha * L);
    float bse  = fmaf(xv, sinv, p.delta);            // > 0
    return (p.rhalf ? fast_sqrt(bse)
                    : fast_exp2(p.r * fast_log2(bse))) - p.dr;
}

__device__ __forceinline__ float horner4(float M, float4 v) {
    M = OMS_C * M + S_C * v.x;
    M = OMS_C * M + S_C * v.y;
    M = OMS_C * M + S_C * v.z;
    M = OMS_C * M + S_C * v.w;
    return M;
}

__global__ __launch_bounds__(BLOCK) void pcen_kernel(
    const float* __restrict__ x,
    const float* __restrict__ alpha_p,
    const float* __restrict__ delta_p,
    const float* __restrict__ r_p,
    float* __restrict__ out)
{
    __shared__ __align__(16) float buf[BUFSZ];
    __shared__ float As[BLOCK + 3];     // As[t+3] = A_t; As[0..2] = halo/boundary

    const int u   = blockIdx.x;         // unit = 4*row + q
    const int tid = threadIdx.x;
    const int row = u >> 2;
    const int q   = u & 3;

    const uint32_t sb = (uint32_t)__cvta_generic_to_shared(buf);

    // ---- stage this quarter (+24-float halo for q>0) via cp.async ----
    {
        const float* src = x + (size_t)row * T_LEN + q * QTR - (q ? HALO : 0);
        const int nch = q ? 256 : 250;
        const int Ls  = q ? 0 : HALO;
        #pragma unroll
        for (int m = tid; m < nch; m += BLOCK) {
            int L = Ls + 4 * m;
            cp_async16(sb + 4u * (uint32_t)P16(L), src + 4 * m);
        }
    }
    asm volatile("cp.async.commit_group;\n" ::: "memory");

    // scalar params (overlap with async loads)
    Params p;
    {
        float alpha = fminf(fmaxf(alpha_p[0], 0.01f), 0.99f);
        p.delta  = fabsf(delta_p[0]) + 1e-6f;
        p.r      = fminf(fmaxf(r_p[0], 0.01f), 1.0f);
        p.rhalf  = (p.r == 0.5f);
        p.dr     = p.rhalf ? fast_sqrt(p.delta)
                           : fast_exp2(p.r * fast_log2(p.delta));
        p.nalpha = -alpha;
    }

    asm volatile("cp.async.wait_group 0;\n" ::: "memory");
    __syncthreads();                    // BAR1: data staged & visible

    const bool act = tid < NSEG;
    const int  s0  = SEG * tid;         // segment start within quarter

    // ---- A pass: zero-seeded Horner over own 8 values ----
    if (act) {
        float A = 0.0f;
        #pragma unroll
        for (int g = 0; g < 2; g++) {
            float4 v = *(const float4*)&buf[P16(HALO + s0 + 4 * g)];
            A = horner4(A, v);
        }
        As[tid + 3] = A;
    } else if (q) {
        // threads 125..127: halo segment A's (local [0,8),[8,16),[16,24))
        const int h0 = (tid - NSEG) * SEG;
        float A = 0.0f;
        #pragma unroll
        for (int g = 0; g < 2; g++) {
            float4 v = *(const float4*)&buf[P16(h0 + 4 * g)];
            A = horner4(A, v);
        }
        As[tid - NSEG] = A;             // As[0..2]
    } else if (tid == 127) {
        // row start: generic window then yields exact seeds for tids 0/1/2
        As[0] = 0.0f;
        As[1] = 0.0f;
        As[2] = buf[P16(HALO)];         // x[0]
    }
    __syncthreads();                    // BAR2: As visible

    // ---- window combine + compute (generic for ALL threads) ----
    if (act) {
        float M = fmaf(LAM8, fmaf(LAM8, As[tid], As[tid + 1]), As[tid + 2]);
        #pragma unroll
        for (int g = 0; g < 2; g++) {
            float4 v = *(const float4*)&buf[P16(HALO + s0 + 4 * g)];
            float4 o;
            M = OMS_C * M + S_C * v.x;  o.x = pcen_elem(v.x, M, p);
            M = OMS_C * M + S_C * v.y;  o.y = pcen_elem(v.y, M, p);
            M = OMS_C * M + S_C * v.z;  o.z = pcen_elem(v.z, M, p);
            M = OMS_C * M + S_C * v.w;  o.w = pcen_elem(v.w, M, p);
            *(float4*)&buf[P16(HALO + s0 + 4 * g)] = o;
        }
    }
    __syncthreads();                    // BAR3: results staged

    // ---- coalesced writeback ----
    {
        float* __restrict__ outr = out + (size_t)row * T_LEN + q * QTR;
        #pragma unroll
        for (int i = tid; i < 250; i += BLOCK) {
            float4 v = *(const float4*)&buf[P16(HALO + 4 * i)];
            *(float4*)(outr + 4 * i) = v;
        }
    }
}

extern "C" void kernel_launch(void* const* d_in, const int* in_sizes, int n_in,
                              void* d_out, int out_size) {
    const float* mel   = (const float*)d_in[0];
    const float* alpha = (const float*)d_in[1];
    const float* delta = (const float*)d_in[2];
    const float* r     = (const float*)d_in[3];
    float* out = (float*)d_out;

    int rows = out_size / T_LEN;       // 16384
    pcen_kernel<<<4 * rows, BLOCK>>>(mel, alpha, delta, r, out);
}

// round 13
// speedup vs baseline: 1.2630x; 1.0454x over previous
#include <cuda_runtime.h>
#include <cuda_bf16.h>
#include <cstdint>

#define T_LEN 4000
#define HALF  2000
#define BLOCK 128
#define SEG   16
#define NSEG  125
#define HALO  32
#define P16(i) ((i) + (((i) >> 5) << 2))
#define IBUFSZ 2284   // P16(HALO + HALF - 1) + 1 -> 9136 B (read-only input)
#define OBUFSZ 2248   // P16(HALF - 1) + 1       -> 8992 B (output staging)

#define S_C    (512.0f / 1323.0f)
#define OMS_C  (1.0f - 512.0f / 1323.0f)
#define LAMBDA 3.98320e-4f      // OMS_C^16

__device__ __forceinline__ float fast_exp2(float x) {
    float y; asm("ex2.approx.ftz.f32 %0, %1;" : "=f"(y) : "f"(x)); return y;
}
__device__ __forceinline__ float fast_log2(float x) {
    float y; asm("lg2.approx.ftz.f32 %0, %1;" : "=f"(y) : "f"(x)); return y;
}
__device__ __forceinline__ float fast_sqrt(float x) {
    float y; asm("sqrt.approx.ftz.f32 %0, %1;" : "=f"(y) : "f"(x)); return y;
}
__device__ __forceinline__ void cp_async16(uint32_t dst, const float* src) {
    asm volatile("cp.async.cg.shared.global [%0], [%1], 16;\n" :: "r"(dst), "l"(src));
}

struct Params { float delta, r, dr, nalpha; bool rhalf; };

__device__ __forceinline__ float pcen_elem(float xv, float M, const Params& p) {
    float L    = fast_log2(1e-6f + M);
    float sinv = fast_exp2(p.nalpha * L);
    float bse  = fmaf(xv, sinv, p.delta);            // > 0
    return (p.rhalf ? fast_sqrt(bse)
                    : fast_exp2(p.r * fast_log2(bse))) - p.dr;
}

__device__ __forceinline__ float horner4(float M, float4 v) {
    M = OMS_C * M + S_C * v.x;
    M = OMS_C * M + S_C * v.y;
    M = OMS_C * M + S_C * v.z;
    M = OMS_C * M + S_C * v.w;
    return M;
}

__global__ __launch_bounds__(BLOCK) void pcen_kernel(
    const float* __restrict__ x,
    const float* __restrict__ alpha_p,
    const float* __restrict__ delta_p,
    const float* __restrict__ r_p,
    float* __restrict__ out)
{
    __shared__ __align__(16) float ibuf[IBUFSZ];   // staged input (read-only after BAR1)
    __shared__ __align__(16) float obuf[OBUFSZ];   // output staging

    const int u    = blockIdx.x;        // unit = 2*row + half
    const int tid  = threadIdx.x;
    const int row  = u >> 1;
    const int half = u & 1;

    const uint32_t sb = (uint32_t)__cvta_generic_to_shared(ibuf);

    // ---- stage this half-row (half1 includes 32-float halo) via cp.async ----
    {
        const float* src = x + (size_t)row * T_LEN + (half ? (HALF - HALO) : 0);
        const int nch = half ? 508 : 500;
        const int Ls  = half ? 0 : HALO;
        #pragma unroll
        for (int m = tid; m < nch; m += BLOCK) {
            int L = Ls + 4 * m;
            cp_async16(sb + 4u * (uint32_t)P16(L), src + 4 * m);
        }
    }
    asm volatile("cp.async.commit_group;\n" ::: "memory");

    // scalar params (overlap with async loads)
    Params p;
    {
        float alpha = fminf(fmaxf(alpha_p[0], 0.01f), 0.99f);
        p.delta  = fabsf(delta_p[0]) + 1e-6f;
        p.r      = fminf(fmaxf(r_p[0], 0.01f), 1.0f);
        p.rhalf  = (p.r == 0.5f);
        p.dr     = p.rhalf ? fast_sqrt(p.delta)
                           : fast_exp2(p.r * fast_log2(p.delta));
        p.nalpha = -alpha;
    }

    asm volatile("cp.async.wait_group 0;\n" ::: "memory");
    __syncthreads();                    // BAR1: data staged & visible (ibuf read-only now)

    const bool act  = tid < NSEG;
    const int  lane = tid & 31;
    // clamp inactive threads (125..127) to a valid segment so they can
    // participate in the full-mask shuffles below; their A is discarded.
    const int  seg  = act ? tid : (NSEG - 1);
    const int  w0   = HALO + SEG * seg; // segment start in ibuf (in-bounds for all)

    // ---- A pass: ALL threads (full-mask shfl participation) ----
    float A = 0.0f;
    #pragma unroll
    for (int g = 0; g < 4; g++) {
        float4 v = *(const float4*)&ibuf[P16(w0 + 4 * g)];
        A = horner4(A, v);
    }
    float A1 = __shfl_up_sync(0xffffffffu, A, 1);
    float A2 = __shfl_up_sync(0xffffffffu, A, 2);

    if (act) {
        // ---- window: M just before segment start ----
        float M;
        if (lane >= 2) {
            M = fmaf(LAMBDA, A2, A1);                  // A_{t-1} + lam*A_{t-2}
        } else if (half == 0 && tid == 0) {
            M = ibuf[P16(HALO)];                       // seed -> M[0] = x[0] exact
        } else if (half == 0 && tid == 1) {
            M = fmaf(LAMBDA, ibuf[P16(HALO)], A1);     // exact M[15] = A_0 + lam*x0
        } else {
            // warp-boundary lanes (and half1 tids 0/1): 32-tap raw window
            M = 0.0f;
            #pragma unroll
            for (int g = 0; g < 8; g++) {
                float4 v = *(const float4*)&ibuf[P16(w0 - HALO + 4 * g)];
                M = horner4(M, v);
            }
        }

        // ---- compute 16 elems -> separate output buffer ----
        const int o0 = SEG * tid;
        #pragma unroll
        for (int g = 0; g < 4; g++) {
            float4 v = *(const float4*)&ibuf[P16(w0 + 4 * g)];
            float4 o;
            M = OMS_C * M + S_C * v.x;  o.x = pcen_elem(v.x, M, p);
            M = OMS_C * M + S_C * v.y;  o.y = pcen_elem(v.y, M, p);
            M = OMS_C * M + S_C * v.z;  o.z = pcen_elem(v.z, M, p);
            M = OMS_C * M + S_C * v.w;  o.w = pcen_elem(v.w, M, p);
            *(float4*)&obuf[P16(o0 + 4 * g)] = o;
        }
    }
    __syncthreads();                    // BAR2: outputs staged

    // ---- coalesced writeback ----
    {
        float* __restrict__ outr = out + (size_t)row * T_LEN + half * HALF;
        #pragma unroll
        for (int i = tid; i < 500; i += BLOCK) {
            float4 v = *(const float4*)&obuf[P16(4 * i)];
            *(float4*)(outr + 4 * i) = v;
        }
    }
}

extern "C" void kernel_launch(void* const* d_in, const int* in_sizes, int n_in,
                              void* d_out, int out_size) {
    const float* mel   = (const float*)d_in[0];
    const float* alpha = (const float*)d_in[1];
    const float* delta = (const float*)d_in[2];
    const float* r     = (const float*)d_in[3];
    float* out = (float*)d_out;

    int rows = out_size / T_LEN;       // 16384
    pcen_kernel<<<2 * rows, BLOCK>>>(mel, alpha, delta, r, out);
}

// round 14
// speedup vs baseline: 1.3116x; 1.0385x over previous
#include <cuda_runtime.h>
#include <cuda_bf16.h>
#include <cstdint>

#define T_LEN 4000
#define HALF  2000
#define BLOCK 128
#define SEG   16
#define NSEG  125
#define HALO  32
#define P16(i) ((i) + (((i) >> 5) << 2))
#define BUFSZ 2284   // P16(HALO + HALF - 1) + 1  -> 9136 bytes

#define S_C    (512.0f / 1323.0f)
#define OMS_C  (1.0f - 512.0f / 1323.0f)
#define LAMBDA 3.98320e-4f      // OMS_C^16

__device__ __forceinline__ float fast_exp2(float x) {
    float y; asm("ex2.approx.ftz.f32 %0, %1;" : "=f"(y) : "f"(x)); return y;
}
__device__ __forceinline__ float fast_log2(float x) {
    float y; asm("lg2.approx.ftz.f32 %0, %1;" : "=f"(y) : "f"(x)); return y;
}
__device__ __forceinline__ float fast_sqrt(float x) {
    float y; asm("sqrt.approx.ftz.f32 %0, %1;" : "=f"(y) : "f"(x)); return y;
}
__device__ __forceinline__ void cp_async16(uint32_t dst, const float* src) {
    asm volatile("cp.async.cg.shared.global [%0], [%1], 16;\n" :: "r"(dst), "l"(src));
}
__device__ __forceinline__ void stg_cs_128(float* p4, float4 v) {
    asm volatile("st.global.cs.v4.f32 [%0], {%1, %2, %3, %4};\n"
                 :: "l"(p4), "f"(v.x), "f"(v.y), "f"(v.z), "f"(v.w) : "memory");
}

struct Params { float delta, r, dr, nalpha; bool rhalf; };

__device__ __forceinline__ float pcen_elem(float xv, float M, const Params& p) {
    float L    = fast_log2(1e-6f + M);
    float sinv = fast_exp2(p.nalpha * L);
    float bse  = fmaf(xv, sinv, p.delta);            // > 0
    return (p.rhalf ? fast_sqrt(bse)
                    : fast_exp2(p.r * fast_log2(bse))) - p.dr;
}

__device__ __forceinline__ float horner4(float M, float4 v) {
    M = OMS_C * M + S_C * v.x;
    M = OMS_C * M + S_C * v.y;
    M = OMS_C * M + S_C * v.z;
    M = OMS_C * M + S_C * v.w;
    return M;
}

__global__ __launch_bounds__(BLOCK) void pcen_kernel(
    const float* __restrict__ x,
    const float* __restrict__ alpha_p,
    const float* __restrict__ delta_p,
    const float* __restrict__ r_p,
    float* __restrict__ out)
{
    __shared__ __align__(16) float buf[BUFSZ];
    __shared__ float As[BLOCK];         // As[t+2] = A_t; As[0..1] = halo A's (half1)

    const int u    = blockIdx.x;        // unit = 2*row + half
    const int tid  = threadIdx.x;
    const int row  = u >> 1;
    const int half = u & 1;

    const uint32_t sb = (uint32_t)__cvta_generic_to_shared(buf);

    // ---- stage this half-row (half1 includes 32-float halo) via cp.async ----
    {
        const float* src = x + (size_t)row * T_LEN + (half ? (HALF - HALO) : 0);
        const int nch = half ? 508 : 500;
        const int Ls  = half ? 0 : HALO;
        #pragma unroll
        for (int m = tid; m < nch; m += BLOCK) {
            int L = Ls + 4 * m;
            cp_async16(sb + 4u * (uint32_t)P16(L), src + 4 * m);
        }
    }
    asm volatile("cp.async.commit_group;\n" ::: "memory");

    // scalar params (overlap with async loads)
    Params p;
    {
        float alpha = fminf(fmaxf(alpha_p[0], 0.01f), 0.99f);
        p.delta  = fabsf(delta_p[0]) + 1e-6f;
        p.r      = fminf(fmaxf(r_p[0], 0.01f), 1.0f);
        p.rhalf  = (p.r == 0.5f);
        p.dr     = p.rhalf ? fast_sqrt(p.delta)
                           : fast_exp2(p.r * fast_log2(p.delta));
        p.nalpha = -alpha;
    }

    asm volatile("cp.async.wait_group 0;\n" ::: "memory");
    __syncthreads();                    // BAR1: data staged & visible

    const bool act = tid < NSEG;
    const int  w0  = SEG * tid;         // thread's segment start (local, pre-halo)

    // ---- A pass: zero-seeded Horner over own 16 values ----
    if (act) {
        float A = 0.0f;
        #pragma unroll
        for (int q = 0; q < 4; q++) {
            float4 v = *(const float4*)&buf[P16(HALO + w0 + 4 * q)];
            A = horner4(A, v);
        }
        As[tid + 2] = A;
    } else if (half && tid < NSEG + 2) {
        // threads 125,126 compute halo segment A's (half1 only)
        const int h0 = (tid - NSEG) * SEG;     // 0 or 16 within halo
        float A = 0.0f;
        #pragma unroll
        for (int q = 0; q < 4; q++) {
            float4 v = *(const float4*)&buf[P16(h0 + 4 * q)];
            A = horner4(A, v);
        }
        As[tid - NSEG] = A;                    // As[0], As[1]
    }
    __syncthreads();                    // BAR2: As visible

    // ---- window combine: M just before segment start ----
    float M = 0.0f;
    if (act) {
        if (half || tid >= 2) {
            M = fmaf(LAMBDA, As[tid], As[tid + 1]);
        } else if (tid == 0) {
            M = buf[P16(HALO)];         // seed: first step gives M[0]=x[0]
        } else {                        // tid == 1: exact M[15] = A_0 + lam*x0
            M = fmaf(LAMBDA, buf[P16(HALO)], As[2]);
        }
    }

    // ---- compute 16 elems in place (own region only -> no cross-thread hazard) ----
    if (act) {
        #pragma unroll
        for (int q = 0; q < 4; q++) {
            float4 v = *(const float4*)&buf[P16(HALO + w0 + 4 * q)];
            float4 o;
            M = OMS_C * M + S_C * v.x;  o.x = pcen_elem(v.x, M, p);
            M = OMS_C * M + S_C * v.y;  o.y = pcen_elem(v.y, M, p);
            M = OMS_C * M + S_C * v.z;  o.z = pcen_elem(v.z, M, p);
            M = OMS_C * M + S_C * v.w;  o.w = pcen_elem(v.w, M, p);
            *(float4*)&buf[P16(HALO + w0 + 4 * q)] = o;
        }
    }
    __syncthreads();                    // BAR3: results ready

    // ---- coalesced writeback (streaming stores: write-once data) ----
    {
        float* __restrict__ outr = out + (size_t)row * T_LEN + half * HALF;
        #pragma unroll
        for (int i = tid; i < 500; i += BLOCK) {
            float4 v = *(const float4*)&buf[P16(HALO + 4 * i)];
            stg_cs_128(outr + 4 * i, v);
        }
    }
}

extern "C" void kernel_launch(void* const* d_in, const int* in_sizes, int n_in,
                              void* d_out, int out_size) {
    const float* mel   = (const float*)d_in[0];
    const float* alpha = (const float*)d_in[1];
    const float* delta = (const float*)d_in[2];
    const float* r     = (const float*)d_in[3];
    float* out = (float*)d_out;

    int rows = out_size / T_LEN;       // 16384
    pcen_kernel<<<2 * rows, BLOCK>>>(mel, alpha, delta, r, out);
}